// round 14
// baseline (speedup 1.0000x reference)
#include <cuda_runtime.h>

#define BS_    128
#define NF_    4
#define P_LO_  1024
#define P_HI_  16384
#define K_     9
#define NC_    36

// Allocation-free scratch.
__device__ int g_cls_count[NC_];
__device__ int g_cls_list[NC_][BS_];
__device__ unsigned long long g_pack[P_HI_];   // per-point shuffle descriptor

// Merged prepass.
//  CTAs 0..63 : pack shuffle descriptors. Warp W = cta*8+wid covers hi rows
//               {2h,2h+1}, cols [16t,16t+16). Window base (r0,c0) = warp-min
//               of actual neighbor rows/cols. Shape mode (warp-uniform):
//                 mode0: rspan<=3 && cspan<=7  -> slot = dr*8 + dc
//                 mode1: rspan<=4 && cspan<=5  -> slot = dr*6 + dc (<=29)
//                 mode2: fallback (global gather in main kernel)
//               pk bits: sl_k @5k (k<9), r0 @45, c0 @50, mode @55.
//               nbr rows are staged through smem via coalesced int4 loads
//               (direct per-lane reads stride 36B -> 9 wavefronts/instr).
//  CTAs 64..68: class lists, one warp per class (ballot keeps batch order).
__global__ void prepass_kernel(const int* __restrict__ cls_ids,
                               const int* __restrict__ nbr) {
    __shared__ int snb[8][288];               // per-warp staging (9216 B)
    const int cta  = blockIdx.x;
    const int tid  = threadIdx.x;
    const int lane = tid & 31;
    if (cta < 64) {
        const int wid = tid >> 5;
        const int W = cta * 8 + wid;
        const int h = W >> 3, t = W & 7;
        const int half = lane >> 4, j = lane & 15;
        const int row = 2 * h + half;
        const int p = row * 128 + 16 * t + j;

        // stage this half-warp's 144 ints (576B contiguous, 16B aligned)
        const int4* s4 = reinterpret_cast<const int4*>(
            nbr + (size_t)(row * 128 + 16 * t) * K_);
        int4* d4 = reinterpret_cast<int4*>(snb[wid] + half * 144);
        d4[j]      = s4[j];
        d4[j + 16] = s4[j + 16];
        if (j < 4) d4[j + 32] = s4[j + 32];
        __syncwarp();
        const int* my = snb[wid] + half * 144 + j * 9;

        int r[K_], c[K_];
        int rmin = 32, cmin = 32, rmax = -1, cmax = -1;
        #pragma unroll
        for (int k = 0; k < K_; k++) {
            int v = my[k];
            r[k] = v >> 5; c[k] = v & 31;
            rmin = min(rmin, r[k]);  rmax = max(rmax, r[k]);
            cmin = min(cmin, c[k]);  cmax = max(cmax, c[k]);
        }
        #pragma unroll
        for (int o = 16; o; o >>= 1) {
            rmin = min(rmin, __shfl_xor_sync(0xffffffffu, rmin, o));
            rmax = max(rmax, __shfl_xor_sync(0xffffffffu, rmax, o));
            cmin = min(cmin, __shfl_xor_sync(0xffffffffu, cmin, o));
            cmax = max(cmax, __shfl_xor_sync(0xffffffffu, cmax, o));
        }
        const int rspan = rmax - rmin, cspan = cmax - cmin;
        int mode;
        if (rspan <= 3 && cspan <= 7)      mode = 0;
        else if (rspan <= 4 && cspan <= 5) mode = 1;
        else                               mode = 2;

        unsigned long long pk = ((unsigned long long)rmin << 45) |
                                ((unsigned long long)cmin << 50) |
                                ((unsigned long long)mode << 55);
        if (mode < 2) {
            #pragma unroll
            for (int k = 0; k < K_; k++) {
                int dr = r[k] - rmin, dc = c[k] - cmin;
                unsigned long long sl =
                    (unsigned long long)(mode == 0 ? dr * 8 + dc : dr * 6 + dc);
                pk |= sl << (5 * k);
            }
        }
        g_pack[p] = pk;
    } else {
        const int w = (cta - 64) * 8 + (tid >> 5);
        if (w < NC_) {
            int base = 0;
            #pragma unroll
            for (int chunk = 0; chunk < BS_ / 32; chunk++) {
                int i = chunk * 32 + lane;
                int v = cls_ids[i];
                unsigned m = __ballot_sync(0xffffffffu, v == w);
                if (v == w)
                    g_cls_list[w][base + __popc(m & ((1u << lane) - 1))] = i;
                base += __popc(m);
            }
            if (lane == 0) g_cls_count[w] = base;
        }
    }
}

// Warp-autonomous main kernel: no block barriers. Weights are staged through
// per-warp smem with coalesced LDG.128 (direct per-lane reads stride 36B ->
// 9 wavefronts per instr; staged path is 12 wavefronts per warp total, and
// the 9 LDS reads are bank-conflict-free: addr = half*144 + j*9 + k, with
// 9 coprime to 32 and the +144 == +16 half offset giving disjoint residues).
__global__ void __launch_bounds__(256, 5)
upsample_kernel(const float* __restrict__ x,
                const int*   __restrict__ nbr,
                const float* __restrict__ wmap,
                const float* __restrict__ blo,
                const float* __restrict__ bhi,
                float*       __restrict__ out)
{
    __shared__ float sw[8][288];              // per-warp weight staging (9216 B)

    const int f = blockIdx.y;
    const int c = blockIdx.z;
    const int n = g_cls_count[c];
    if (n == 0) return;

    const int tid  = threadIdx.x;
    const int lane = tid & 31;
    const int wid  = tid >> 5;
    const int W = blockIdx.x * 8 + wid;
    const int h = W >> 3, t = W & 7;
    const int half = lane >> 4, j = lane & 15;
    const int row = 2 * h + half;
    const int p = row * 128 + 16 * t + j;

    // ---- coalesced weight staging ----
    const float* wreg = wmap +
        (((size_t)c * NF_ + f) * P_HI_ + (size_t)(row * 128 + 16 * t)) * K_;
    {
        const float4* s4 = reinterpret_cast<const float4*>(wreg);
        float4* d4 = reinterpret_cast<float4*>(sw[wid] + half * 144);
        d4[j]      = s4[j];
        d4[j + 16] = s4[j + 16];
        if (j < 4) d4[j + 32] = s4[j + 32];
    }

    const unsigned long long pk = g_pack[p];
    const float bh = bhi[((size_t)c * NF_ + f) * P_HI_ + p];

    __syncwarp();
    float wv[K_];
    {
        const float* my = sw[wid] + half * 144 + j * 9;
        #pragma unroll
        for (int k = 0; k < K_; k++) wv[k] = my[k];
    }

    const float* blo_cf = blo + ((size_t)c * NF_ + f) * P_LO_;
    const float* x_f    = x   + (size_t)f * P_LO_;
    float*       obase  = out + (size_t)f * P_HI_ + p;

    const int mode = (int)((pk >> 55) & 3);

    if (mode < 2) {
        const int r0 = (int)((pk >> 45) & 31);
        const int c0 = (int)((pk >> 50) & 31);
        int sl[K_];
        #pragma unroll
        for (int k = 0; k < K_; k++) sl[k] = (int)((pk >> (5 * k)) & 31);

        // this lane's staged lo point (slot -> grid; clamped slots never referenced)
        const int srow = min(r0 + (mode == 0 ? (lane >> 3) : lane / 6), 31);
        const int scol = min(c0 + (mode == 0 ? (lane & 7)  : lane % 6), 31);
        const int sidx = srow * 32 + scol;

        const float blo_s = blo_cf[sidx];
        const float* xbase = x_f + sidx;

        int b = g_cls_list[c][0];
        float xv = xbase[(size_t)b * (NF_ * P_LO_)];
        for (int s = 0; s < n; s++) {
            const float y = xv - blo_s;
            const int bc = b;
            if (s + 1 < n) {
                b  = g_cls_list[c][s + 1];
                xv = xbase[(size_t)b * (NF_ * P_LO_)];
            }
            float acc = bh;
            #pragma unroll
            for (int k = 0; k < K_; k++)
                acc = fmaf(wv[k], __shfl_sync(0xffffffffu, y, sl[k]), acc);
            obase[(size_t)bc * (NF_ * P_HI_)] = acc;
        }
    } else {
        // Safety net: direct global gather (expected never / rarely taken).
        int nb[K_];
        float blo_nb[K_];
        #pragma unroll
        for (int k = 0; k < K_; k++) {
            nb[k]     = nbr[p * K_ + k];
            blo_nb[k] = blo_cf[nb[k]];
        }
        for (int s = 0; s < n; s++) {
            const int b = g_cls_list[c][s];
            const float* xs = x_f + (size_t)b * (NF_ * P_LO_);
            float acc = bh;
            #pragma unroll
            for (int k = 0; k < K_; k++)
                acc = fmaf(wv[k], xs[nb[k]] - blo_nb[k], acc);
            obase[(size_t)b * (NF_ * P_HI_)] = acc;
        }
    }
}

extern "C" void kernel_launch(void* const* d_in, const int* in_sizes, int n_in,
                              void* d_out, int out_size) {
    const float* x    = (const float*)d_in[0];   // (BS, NF*P_LO) f32
    const int*   cls  = (const int*)  d_in[1];   // (BS,) i32
    const int*   nbr  = (const int*)  d_in[2];   // (P_HI, K) i32
    const float* wmap = (const float*)d_in[3];   // (NC, NF, P_HI, K) f32
    const float* blo  = (const float*)d_in[4];   // (NC, NF, P_LO) f32
    const float* bhi  = (const float*)d_in[5];   // (NC, NF, P_HI) f32
    float* out = (float*)d_out;                  // (BS, NF, P_HI) f32

    prepass_kernel<<<69, 256>>>(cls, nbr);
    dim3 grid(64, NF_, NC_);
    upsample_kernel<<<grid, 256>>>(x, nbr, wmap, blo, bhi, out);
}